// round 1
// baseline (speedup 1.0000x reference)
#include <cuda_runtime.h>
#include <cstdint>

#define TPB 128
#define XPAD 62   // per-problem smem stride in floats (even: 8B-aligned float2; 62%32=30 -> only 2-way bank conflicts)

typedef unsigned long long ull;

// ---- packed fp32x2 helpers (sm_100+ has FFMA2 via PTX fma.rn.f32x2) ----
__device__ __forceinline__ ull pk(float lo, float hi) {
    ull r; asm("mov.b64 %0, {%1, %2};" : "=l"(r) : "f"(lo), "f"(hi)); return r;
}
__device__ __forceinline__ float lo2(ull v) { return __uint_as_float((unsigned)v); }
__device__ __forceinline__ float hi2(ull v) { return __uint_as_float((unsigned)(v >> 32)); }
__device__ __forceinline__ ull fma2(ull a, ull b, ull c) {
    ull d; asm("fma.rn.f32x2 %0, %1, %2, %3;" : "=l"(d) : "l"(a), "l"(b), "l"(c)); return d;
}

// One thread = one batch problem.
// Math:  S_ij = x_i^T M x_j + x_i.u + r.x_j + c,   M = Wq^T Wk, u = Wq^T bk, r = Wk^T bq, c = bq.bk
//        out_i = (sum_j exp(S_ij) * vsum_j) / (sum_j exp(S_ij)),  vsum_j = wv.x_j + cv
__global__ __launch_bounds__(TPB) void attn_kernel(
    const float* __restrict__ x,
    const float* __restrict__ Wk, const float* __restrict__ bk,
    const float* __restrict__ Wq, const float* __restrict__ bq,
    const float* __restrict__ Wv, const float* __restrict__ bv,
    float* __restrict__ out)
{
    __shared__ float cst[64];            // M[36], u[6], r[6], c, wv[6], cv
    __shared__ float xs[TPB * XPAD];     // staged x, stride-62 padded
    const int t = threadIdx.x;

    // ---- per-block precompute of batch-independent constants (redundant per block, L2-cached) ----
    if (t < 36) {                        // M[a][b] = sum_e Wq[e][a] * Wk[e][b]
        int a = t / 6, b = t % 6; float s = 0.f;
        #pragma unroll
        for (int e = 0; e < 6; e++) s += Wq[e*6 + a] * Wk[e*6 + b];
        cst[t] = s;
    } else if (t < 42) {                 // u[a] = sum_e Wq[e][a] * bk[e]
        int a = t - 36; float s = 0.f;
        #pragma unroll
        for (int e = 0; e < 6; e++) s += Wq[e*6 + a] * bk[e];
        cst[t] = s;
    } else if (t < 48) {                 // r[b] = sum_e bq[e] * Wk[e][b]
        int b = t - 42; float s = 0.f;
        #pragma unroll
        for (int e = 0; e < 6; e++) s += bq[e] * Wk[e*6 + b];
        cst[t] = s;
    } else if (t == 48) {                // c = bq.bk
        float s = 0.f;
        #pragma unroll
        for (int e = 0; e < 6; e++) s += bq[e] * bk[e];
        cst[48] = s;
    } else if (t < 55) {                 // wv[d] = sum_e Wv[e][d]
        int d = t - 49; float s = 0.f;
        #pragma unroll
        for (int e = 0; e < 6; e++) s += Wv[e*6 + d];
        cst[t] = s;
    } else if (t == 55) {                // cv = sum_e bv[e]
        float s = 0.f;
        #pragma unroll
        for (int e = 0; e < 6; e++) s += bv[e];
        cst[55] = s;
    }

    // ---- coalesced staging: 128 problems * 60 floats = 1920 float4 per block ----
    const float4* xg = (const float4*)(x + (size_t)blockIdx.x * (TPB * 60));
    #pragma unroll
    for (int i = 0; i < 15; i++) {
        float4 v = xg[i * TPB + t];
        int g = (i * TPB + t) * 4;       // 60 % 4 == 0 -> a float4 never crosses a problem boundary
        int b = g / 60, e = g % 60;
        float2* dst = (float2*)&xs[b * XPAD + e];   // (b*62+e) even -> 8B aligned
        dst[0] = make_float2(v.x, v.y);
        dst[1] = make_float2(v.z, v.w);
    }
    __syncthreads();

    // ---- load constants into registers ----
    float M[36], uu[6], rr[6], wv[6];
    #pragma unroll
    for (int i = 0; i < 36; i++) M[i] = cst[i];
    #pragma unroll
    for (int i = 0; i < 6; i++) { uu[i] = cst[36 + i]; rr[i] = cst[42 + i]; wv[i] = cst[49 + i]; }
    const float c0 = cst[48], cv = cst[55];

    const float* xp = &xs[t * XPAD];

    // ---- phase 1: per key-pair (j, j+1): G[a] = (M x_j + u)[a], h_j = r.x_j + c, vsum_j ----
    ull G2[6][5];      // G packed over key pairs: (G_j[a], G_{j+1}[a])
    ull hp[5], vp[5];  // (h_j, h_{j+1}), (vsum_j, vsum_{j+1})
    #pragma unroll
    for (int jp = 0; jp < 5; jp++) {
        float g0[6], g1[6];
        #pragma unroll
        for (int a = 0; a < 6; a++) { g0[a] = uu[a]; g1[a] = uu[a]; }
        float h0 = c0, h1 = c0, s0 = cv, s1 = cv;
        #pragma unroll
        for (int d = 0; d < 6; d++) {
            float x0 = xp[jp*12 + d];
            float x1 = xp[jp*12 + 6 + d];
            h0 += rr[d] * x0;  h1 += rr[d] * x1;
            s0 += wv[d] * x0;  s1 += wv[d] * x1;
            #pragma unroll
            for (int a = 0; a < 6; a++) {
                g0[a] += M[a*6 + d] * x0;
                g1[a] += M[a*6 + d] * x1;
            }
        }
        #pragma unroll
        for (int a = 0; a < 6; a++) G2[a][jp] = pk(g0[a], g1[a]);
        hp[jp] = pk(h0, h1);
        vp[jp] = pk(s0, s1);
    }

    // ---- phase 2: per query i: two scores at a time via FFMA2, fused softmax+weighted-sum ----
    const size_t ob = (size_t)(blockIdx.x * TPB + t) * 10;
    #pragma unroll
    for (int i = 0; i < 10; i++) {
        ull X[6];
        #pragma unroll
        for (int a = 0; a < 6; a++) { float xv = xp[i*6 + a]; X[a] = pk(xv, xv); }
        float num = 0.f, den = 0.f;
        #pragma unroll
        for (int jp = 0; jp < 5; jp++) {
            ull s = hp[jp];
            #pragma unroll
            for (int a = 0; a < 6; a++) s = fma2(X[a], G2[a][jp], s);
            float ea = __expf(lo2(s));
            float eb = __expf(hi2(s));
            den += ea + eb;
            num += ea * lo2(vp[jp]);
            num += eb * hi2(vp[jp]);
        }
        out[ob + i] = __fdividef(num, den);
    }
}

extern "C" void kernel_launch(void* const* d_in, const int* in_sizes, int n_in,
                              void* d_out, int out_size) {
    const float* x  = (const float*)d_in[0];
    const float* Wk = (const float*)d_in[1];
    const float* bk = (const float*)d_in[2];
    const float* Wq = (const float*)d_in[3];
    const float* bq = (const float*)d_in[4];
    const float* Wv = (const float*)d_in[5];
    const float* bv = (const float*)d_in[6];
    int B = in_sizes[0] / 60;            // 524288
    int blocks = B / TPB;                // 4096 (divides exactly)
    attn_kernel<<<blocks, TPB>>>(x, Wk, bk, Wq, bq, Wv, bv, (float*)d_out);
}